// round 13
// baseline (speedup 1.0000x reference)
#include <cuda_runtime.h>
#include <math.h>

// Problem constants (fixed shapes from setup_inputs)
#define BS      4
#define NHEAD   8
#define HH_TOT  32          // BS*NHEAD
#define T_LEN   1024
#define CH      64
#define NOBJ    8

// flash tile config (v8: tf32 mma, 2-stage cp.async pipeline, Q in regs)
#define QT      64          // q rows per block
#define KT      64          // k cols per tile
// smem: 2 stages of { K[64][68] | V[64][72] }
#define KPITCH  68
#define VPITCH  72
#define VOFFSET (64 * KPITCH)                 // 4352 (within a stage)
#define SSTR    (64 * KPITCH + 64 * VPITCH)   // 8960 floats per stage
#define SMEM_FLOATS (2 * SSTR)                // 17920
#define SMEM_BYTES  (SMEM_FLOATS * 4)         // 71680

typedef unsigned long long ull;

// ---------------- helpers ----------------
__device__ __forceinline__ ull pk2(float lo, float hi) {
    ull r; asm("mov.b64 %0, {%1, %2};" : "=l"(r) : "f"(lo), "f"(hi)); return r;
}
__device__ __forceinline__ void upk2(ull v, float& lo, float& hi) {
    asm("mov.b64 {%0, %1}, %2;" : "=f"(lo), "=f"(hi) : "l"(v));
}
__device__ __forceinline__ ull fma2(ull a, ull b, ull c) {
    ull d; asm("fma.rn.f32x2 %0, %1, %2, %3;" : "=l"(d) : "l"(a), "l"(b), "l"(c)); return d;
}
__device__ __forceinline__ unsigned tf32r(float x) {
    unsigned u; asm("cvt.rna.tf32.f32 %0, %1;" : "=r"(u) : "f"(x)); return u;
}
__device__ __forceinline__ float tf32f(float x) {
    unsigned u = tf32r(x); return __uint_as_float(u);
}
__device__ __forceinline__ void cp16(unsigned dst, const void* src, int bytes) {
    asm volatile("cp.async.cg.shared.global [%0], [%1], 16, %2;"
                 :: "r"(dst), "l"(src), "r"(bytes));
}
#define CP_COMMIT() asm volatile("cp.async.commit_group;")
#define CP_WAIT0()  asm volatile("cp.async.wait_group 0;")
#define CP_WAIT1()  asm volatile("cp.async.wait_group 1;")

#define MMA_TF32(D, a0, a1, a2, a3, b0, b1)                                    \
    asm volatile(                                                              \
        "mma.sync.aligned.m16n8k8.row.col.f32.tf32.tf32.f32 "                  \
        "{%0,%1,%2,%3}, {%4,%5,%6,%7}, {%8,%9}, {%0,%1,%2,%3};"                \
        : "+f"((D)[0]), "+f"((D)[1]), "+f"((D)[2]), "+f"((D)[3])               \
        : "r"(a0), "r"(a1), "r"(a2), "r"(a3), "r"(b0), "r"(b1))

// ---------------- scratch (device globals; no allocs allowed) ----------------
__device__ float g_Qn[HH_TOT * T_LEN * CH];
__device__ float g_Kn[HH_TOT * T_LEN * CH];
__device__ float g_Vn[HH_TOT * T_LEN * CH];
__device__ float g_Qf[HH_TOT * T_LEN * CH];
__device__ float g_Kf[HH_TOT * T_LEN * CH];
__device__ float g_Vf[HH_TOT * T_LEN * CH];
__device__ float g_anull[HH_TOT * T_LEN * CH];
__device__ float g_afg[HH_TOT * T_LEN * CH];
__device__ int   g_regbox[BS * NOBJ * 4];   // i0,i1,j0,j1 (clamped to 32)
__device__ float g_cnt[BS * T_LEN];
__device__ int   g_nullskip[BS * 16];       // 1 if 64-token strip fully covered

// ---------------- init: zero a_fg; block 0 does bbox prep + counters + skip flags ----------------
__global__ __launch_bounds__(256)
void init_kernel(const float* __restrict__ bb) {
    const int tid = threadIdx.x;
    {
        float4* p = (float4*)g_afg;
        for (int i = blockIdx.x * 256 + tid; i < (HH_TOT * T_LEN * CH) / 4; i += 256 * 256)
            p[i] = make_float4(0.f, 0.f, 0.f, 0.f);
    }
    if (blockIdx.x != 0) return;
    __shared__ int sreg[BS * NOBJ][4];
    __shared__ float scnt[BS * T_LEN];
    if (tid < BS * NOBJ) {
        const float* p = bb + tid * 5;
        float x = p[0], y = p[1], w = p[2], h = p[3];
        int i0 = (int)fminf(31.0f, floorf(y * 32.0f));
        int j0 = (int)fminf(31.0f, floorf(x * 32.0f));
        int hh = (int)fmaxf(1.0f, ceilf(h * 32.0f));
        int ww = (int)fmaxf(1.0f, ceilf(w * 32.0f));
        int i1 = min(32, i0 + hh);
        int j1 = min(32, j0 + ww);
        g_regbox[tid * 4 + 0] = i0;  g_regbox[tid * 4 + 1] = i1;
        g_regbox[tid * 4 + 2] = j0;  g_regbox[tid * 4 + 3] = j1;
        sreg[tid][0] = i0; sreg[tid][1] = i1; sreg[tid][2] = j0; sreg[tid][3] = j1;
    }
    __syncthreads();
    for (int idx = tid; idx < BS * T_LEN; idx += 256) {
        int b = idx / T_LEN, t = idx % T_LEN;
        int i = t >> 5, j = t & 31;
        float c = 0.0f;
        #pragma unroll
        for (int o = 0; o < NOBJ; o++) {
            const int* r = sreg[b * NOBJ + o];
            if (i >= r[0] && i < r[1] && j >= r[2] && j < r[3]) c += 1.0f;
        }
        g_cnt[idx] = c;
        scnt[idx] = c;
    }
    __syncthreads();
    if (tid < BS * 16) {
        int b = tid >> 4, qb = tid & 15;
        int flag = 1;
        for (int k = 0; k < 64; k++)
            if (scnt[b * T_LEN + qb * 64 + k] < 0.5f) { flag = 0; break; }
        g_nullskip[tid] = flag;
    }
}

// ---------------- combine: qkv split + prompt projection GEMM (f32x2) ----------------
__global__ __launch_bounds__(256)
void combine_kernel(const float* __restrict__ qkv, const float* __restrict__ nemb,
                    const float* __restrict__ pemb, const float* __restrict__ W) {
    __shared__ float Ws[64 * 65];
    __shared__ __align__(16) float Es[64 * 68];
    const int g   = blockIdx.x;            // 0..23
    const int t0  = blockIdx.y * 64;
    const int zv  = blockIdx.z;
    const int b   = zv >> 1, var = zv & 1;
    const int head = g / 3, part = g % 3;
    const int cg0  = g * 64;
    const float* emb = (var ? pemb : nemb) + b * 64 * 1024;
    const int tid = threadIdx.x;

    for (int i = tid; i < 4096; i += 256) {
        int c = i >> 6, e = i & 63;
        Ws[c * 65 + e] = W[(cg0 + c) * 64 + e];
    }
    for (int i = tid; i < 4096; i += 256) {
        int e = i >> 6, t = i & 63;
        Es[e * 68 + t] = emb[e * 1024 + t0 + t];
    }
    __syncthreads();

    const int c = tid & 63, tg = tid >> 6;   // tg 0..3, 16 t each
    ull acc2[8];
    #pragma unroll
    for (int i = 0; i < 8; i++) acc2[i] = 0ULL;

    #pragma unroll 4
    for (int e = 0; e < 64; e++) {
        float w = Ws[c * 65 + e];
        ull w2 = pk2(w, w);
        const ull* row = (const ull*)(Es + e * 68 + tg * 16);
        #pragma unroll
        for (int k = 0; k < 8; k++) acc2[k] = fma2(w2, row[k], acc2[k]);
    }
    __syncthreads();
    const float* qk = qkv + (size_t)b * 1536 * 1024 + (size_t)cg0 * 1024 + t0;
    for (int i = tid; i < 4096; i += 256) {
        int cc = i >> 6, t = i & 63;
        Es[cc * 68 + t] = qk[cc * 1024 + t];
    }
    __syncthreads();

    float* dst;
    if (var == 0) dst = (part == 0 ? g_Qn : (part == 1 ? g_Kn : g_Vn));
    else          dst = (part == 0 ? g_Qf : (part == 1 ? g_Kf : g_Vf));
    dst += (b * NHEAD + head) * T_LEN * CH;
    const float sc = (part == 0) ? 0.125f : 1.0f;   // scale^2 folded into Q
    #pragma unroll
    for (int k = 0; k < 8; k++) {
        float a0, a1;
        upk2(acc2[k], a0, a1);
        int t = tg * 16 + 2 * k;
        dst[(t0 + t)     * CH + c] = tf32f((a0 + Es[c * 68 + t])     * sc);
        dst[(t0 + t + 1) * CH + c] = tf32f((a1 + Es[c * 68 + t + 1]) * sc);
    }
}

// ---------------- merged flash kernel: tf32 mma, 2-stage pipeline, Q in regs ----------------
// z=0: null attention; z=1..8: fg object z-1 (region-restricted).
// 128 threads = 4 warps; warp w owns q-rows [16w, 16w+16).
__global__ __launch_bounds__(128, 3)
void flash_kernel() {
    extern __shared__ float sm[];
    const int z  = blockIdx.z;
    const int bh = blockIdx.y;
    const int qbase = blockIdx.x * QT;
    int i0 = 0, j00 = 0, rw = 32, nR = T_LEN;
    const float *Qp, *Kp, *Vp;
    if (z == 0) {
        if (g_nullskip[(bh >> 3) * 16 + blockIdx.x]) return;   // a_null unused here
        Qp = g_Qn + (size_t)bh * T_LEN * CH;
        Kp = g_Kn + (size_t)bh * T_LEN * CH;
        Vp = g_Vn + (size_t)bh * T_LEN * CH;
    } else {
        const int o = z - 1, b = bh >> 3;
        const int* box = g_regbox + (b * NOBJ + o) * 4;
        i0 = box[0]; j00 = box[2];
        rw = box[3] - j00;
        nR = (box[1] - i0) * rw;
        if (qbase >= nR) return;
        Qp = g_Qf + (size_t)bh * T_LEN * CH;
        Kp = g_Kf + (size_t)bh * T_LEN * CH;
        Vp = g_Vf + (size_t)bh * T_LEN * CH;
    }
    const int tid  = threadIdx.x;
    const int w    = tid >> 5, lane = tid & 31;
    const int la   = lane & 3, lg = lane >> 2;

    const unsigned smem_u = (unsigned)__cvta_generic_to_shared(sm);

    // ---- stage Q through stage-1 K area, then K0/V0 into stage 0 ----
    #pragma unroll
    for (int it = 0; it < 8; it++) {
        int idx = tid + it * 128;
        int r = idx >> 4, c4 = idx & 15;
        int u = qbase + r;
        const float* src = Qp;
        int bytes = 0;
        if (u < nR) {
            int t = (z == 0) ? u : ((i0 + u / rw) * 32 + j00 + u % rw);
            src = Qp + (size_t)t * CH + c4 * 4;
            bytes = 16;
        }
        cp16(smem_u + (SSTR + r * KPITCH + c4 * 4) * 4, src, bytes);
    }
    CP_COMMIT();
    // issue K0/V0 into stage 0
    #pragma unroll
    for (int it = 0; it < 8; it++) {
        int idx = tid + it * 128;
        int s = idx >> 4, c4 = idx & 15;
        const float *ksrc = Kp, *vsrc = Vp;
        int bytes = 0;
        if (s < nR) {
            int t = (z == 0) ? s : ((i0 + s / rw) * 32 + j00 + s % rw);
            ksrc = Kp + (size_t)t * CH + c4 * 4;
            vsrc = Vp + (size_t)t * CH + c4 * 4;
            bytes = 16;
        }
        cp16(smem_u + (s * KPITCH + c4 * 4) * 4, ksrc, bytes);
        cp16(smem_u + (VOFFSET + s * VPITCH + c4 * 4) * 4, vsrc, bytes);
    }
    CP_COMMIT();
    CP_WAIT1();           // Q group done
    __syncthreads();

    // ---- hoist Q fragments into registers (loop-invariant) ----
    unsigned qa[8][4];
    {
        const unsigned* Qb = (const unsigned*)(sm + SSTR);
        const int aoff_lo = (16 * w + lg) * KPITCH + la;
        const int aoff_hi = aoff_lo + 8 * KPITCH;
        #pragma unroll
        for (int ks = 0; ks < 8; ks++) {
            int kk = ks * 8;
            qa[ks][0] = Qb[aoff_lo + kk];
            qa[ks][1] = Qb[aoff_hi + kk];
            qa[ks][2] = Qb[aoff_lo + kk + 4];
            qa[ks][3] = Qb[aoff_hi + kk + 4];
        }
    }
    __syncthreads();      // all Q reads done before tile-1 prefetch overwrites stage 1

    float o[8][4];
    #pragma unroll
    for (int nt = 0; nt < 8; nt++) { o[nt][0] = o[nt][1] = o[nt][2] = o[nt][3] = 0.0f; }
    float m_lo = -1e30f, m_hi = -1e30f, l_lo = 0.0f, l_hi = 0.0f;

    const int boff  = lg * KPITCH + la;        // K B-frag base (banks 4lg+la)
    const int voff  = la * VPITCH + lg;        // V B-frag base (banks 8la+lg)
    const int srcA  = (lane & ~3) | (la >> 1);
    const int srcA2 = srcA + 2;

    const int nkt = (nR + KT - 1) / KT;
    for (int kt = 0; kt < nkt; kt++) {
        // ---- prefetch next tile into the other stage ----
        if (kt + 1 < nkt) {
            const int st = (kt + 1) & 1;
            #pragma unroll
            for (int it = 0; it < 8; it++) {
                int idx = tid + it * 128;
                int s = idx >> 4, c4 = idx & 15;
                int sg = (kt + 1) * KT + s;
                const float *ksrc = Kp, *vsrc = Vp;
                int bytes = 0;
                if (sg < nR) {
                    int t = (z == 0) ? sg : ((i0 + sg / rw) * 32 + j00 + sg % rw);
                    ksrc = Kp + (size_t)t * CH + c4 * 4;
                    vsrc = Vp + (size_t)t * CH + c4 * 4;
                    bytes = 16;
                }
                cp16(smem_u + (st * SSTR + s * KPITCH + c4 * 4) * 4, ksrc, bytes);
                cp16(smem_u + (st * SSTR + VOFFSET + s * VPITCH + c4 * 4) * 4, vsrc, bytes);
            }
            CP_COMMIT();
            CP_WAIT1();    // current tile's group complete
        } else {
            CP_WAIT0();
        }
        __syncthreads();   // current tile visible to all warps

        const unsigned* KsU = (const unsigned*)(sm + (kt & 1) * SSTR);
        const unsigned* VsU = KsU + VOFFSET;

        // ---- S = Q K^T via mma ----
        float acc[8][4];
        #pragma unroll
        for (int nt = 0; nt < 8; nt++) { acc[nt][0] = acc[nt][1] = acc[nt][2] = acc[nt][3] = 0.0f; }
        #pragma unroll
        for (int ks = 0; ks < 8; ks++) {
            int kk = ks * 8;
            #pragma unroll
            for (int nt = 0; nt < 8; nt++) {
                unsigned b0 = KsU[boff + nt * (8 * KPITCH) + kk];
                unsigned b1 = KsU[boff + nt * (8 * KPITCH) + kk + 4];
                MMA_TF32(acc[nt], qa[ks][0], qa[ks][1], qa[ks][2], qa[ks][3], b0, b1);
            }
        }

        // ---- mask columns beyond region (fg only) ----
        if (z != 0) {
            #pragma unroll
            for (int nt = 0; nt < 8; nt++) {
                int sc = kt * KT + 8 * nt + 2 * la;
                if (sc >= nR)     { acc[nt][0] = -1e30f; acc[nt][2] = -1e30f; }
                if (sc + 1 >= nR) { acc[nt][1] = -1e30f; acc[nt][3] = -1e30f; }
            }
        }

        // ---- online softmax (rows lg / lg+8; reduce across quad lanes) ----
        float mx0 = -1e30f, mx1 = -1e30f;
        #pragma unroll
        for (int nt = 0; nt < 8; nt++) {
            mx0 = fmaxf(mx0, fmaxf(acc[nt][0], acc[nt][1]));
            mx1 = fmaxf(mx1, fmaxf(acc[nt][2], acc[nt][3]));
        }
        mx0 = fmaxf(mx0, __shfl_xor_sync(0xffffffffu, mx0, 1));
        mx0 = fmaxf(mx0, __shfl_xor_sync(0xffffffffu, mx0, 2));
        mx1 = fmaxf(mx1, __shfl_xor_sync(0xffffffffu, mx1, 1));
        mx1 = fmaxf(mx1, __shfl_xor_sync(0xffffffffu, mx1, 2));
        float mn0 = fmaxf(m_lo, mx0), mn1 = fmaxf(m_hi, mx1);
        float co0 = __expf(m_lo - mn0), co1 = __expf(m_hi - mn1);
        m_lo = mn0; m_hi = mn1;
        float rs0 = 0.0f, rs1 = 0.0f;
        #pragma unroll
        for (int nt = 0; nt < 8; nt++) {
            acc[nt][0] = __expf(acc[nt][0] - mn0); rs0 += acc[nt][0];
            acc[nt][1] = __expf(acc[nt][1] - mn0); rs0 += acc[nt][1];
            acc[nt][2] = __expf(acc[nt][2] - mn1); rs1 += acc[nt][2];
            acc[nt][3] = __expf(acc[nt][3] - mn1); rs1 += acc[nt][3];
        }
        rs0 += __shfl_xor_sync(0xffffffffu, rs0, 1);
        rs0 += __shfl_xor_sync(0xffffffffu, rs0, 2);
        rs1 += __shfl_xor_sync(0xffffffffu, rs1, 1);
        rs1 += __shfl_xor_sync(0xffffffffu, rs1, 2);
        l_lo = l_lo * co0 + rs0;
        l_hi = l_hi * co1 + rs1;
        #pragma unroll
        for (int nt = 0; nt < 8; nt++) {
            o[nt][0] *= co0; o[nt][1] *= co0;
            o[nt][2] *= co1; o[nt][3] *= co1;
        }

        // ---- O += P V : A-frags via intra-warp shfl; B direct from row-major V ----
        #pragma unroll
        for (int ks = 0; ks < 8; ks++) {
            int kk = ks * 8;
            float p0 = acc[ks][0], p1 = acc[ks][1], p2 = acc[ks][2], p3 = acc[ks][3];
            float t00 = __shfl_sync(0xffffffffu, p0, srcA);
            float t01 = __shfl_sync(0xffffffffu, p1, srcA);
            float t10 = __shfl_sync(0xffffffffu, p2, srcA);
            float t11 = __shfl_sync(0xffffffffu, p3, srcA);
            float t20 = __shfl_sync(0xffffffffu, p0, srcA2);
            float t21 = __shfl_sync(0xffffffffu, p1, srcA2);
            float t30 = __shfl_sync(0xffffffffu, p2, srcA2);
            float t31 = __shfl_sync(0xffffffffu, p3, srcA2);
            unsigned a0 = tf32r((la & 1) ? t01 : t00);
            unsigned a1 = tf32r((la & 1) ? t11 : t10);
            unsigned a2 = tf32r((la & 1) ? t21 : t20);
            unsigned a3 = tf32r((la & 1) ? t31 : t30);
            const unsigned* vb = VsU + voff + kk * VPITCH;
            #pragma unroll
            for (int nt = 0; nt < 8; nt++) {
                unsigned b0 = vb[8 * nt];
                unsigned b1 = vb[8 * nt + 4 * VPITCH];
                MMA_TF32(o[nt], a0, a1, a2, a3, b0, b1);
            }
        }
        __syncthreads();   // all reads of this stage done before it is overwritten
    }

    // ---- epilogue ----
    float inv0 = 1.0f / l_lo, inv1 = 1.0f / l_hi;
    int u_lo = qbase + 16 * w + lg;
    int u_hi = u_lo + 8;
    if (z == 0) {
        float* Op = g_anull + (size_t)bh * T_LEN * CH;
        #pragma unroll
        for (int nt = 0; nt < 8; nt++) {
            int ch = 8 * nt + 2 * la;
            *(float2*)(Op + (size_t)u_lo * CH + ch) = make_float2(o[nt][0] * inv0, o[nt][1] * inv0);
            *(float2*)(Op + (size_t)u_hi * CH + ch) = make_float2(o[nt][2] * inv1, o[nt][3] * inv1);
        }
    } else {
        float* Ap = g_afg + (size_t)bh * T_LEN * CH;
        int t_lo = 0, t_hi = 0;
        if (u_lo < nR) t_lo = (i0 + u_lo / rw) * 32 + j00 + u_lo % rw;
        if (u_hi < nR) t_hi = (i0 + u_hi / rw) * 32 + j00 + u_hi % rw;
        #pragma unroll
        for (int nt = 0; nt < 8; nt++) {
            int ch = 8 * nt + 2 * la;
            if (u_lo < nR) {
                atomicAdd(Ap + (size_t)t_lo * CH + ch,     o[nt][0] * inv0);
                atomicAdd(Ap + (size_t)t_lo * CH + ch + 1, o[nt][1] * inv0);
            }
            if (u_hi < nR) {
                atomicAdd(Ap + (size_t)t_hi * CH + ch,     o[nt][2] * inv1);
                atomicAdd(Ap + (size_t)t_hi * CH + ch + 1, o[nt][3] * inv1);
            }
        }
    }
}

// ---------------- finalize: select + divide + transpose to (bs, 512, T) ----------------
__global__ __launch_bounds__(256)
void finalize_kernel(float* __restrict__ out) {
    __shared__ float smf[64 * 65];
    const int bh = blockIdx.y;
    const int t0 = blockIdx.x * 64;
    const int b = bh >> 3, h = bh & 7;
    const float* An = g_anull + (size_t)bh * T_LEN * CH;
    const float* Af = g_afg   + (size_t)bh * T_LEN * CH;
    const float* Cn = g_cnt + b * T_LEN;
    const int tid = threadIdx.x;
    for (int i = tid; i < 4096; i += 256) {
        int tt = i >> 6, c = i & 63;
        int t = t0 + tt;
        float cnt = Cn[t];
        float v = (cnt > 0.5f) ? Af[(size_t)t * CH + c] / cnt : An[(size_t)t * CH + c];
        smf[tt * 65 + c] = v;
    }
    __syncthreads();
    float* op = out + (size_t)b * 512 * 1024 + (size_t)h * 64 * 1024 + t0;
    for (int i = tid; i < 4096; i += 256) {
        int c = i >> 6, tt = i & 63;
        op[(size_t)c * 1024 + tt] = smf[tt * 65 + c];
    }
}

// ---------------- launch ----------------
extern "C" void kernel_launch(void* const* d_in, const int* in_sizes, int n_in,
                              void* d_out, int out_size) {
    const float* qkv  = (const float*)d_in[0];
    const float* bb   = (const float*)d_in[1];
    const float* nemb = (const float*)d_in[2];
    const float* pemb = (const float*)d_in[3];
    const float* W    = (const float*)d_in[4];
    float* out = (float*)d_out;

    cudaFuncSetAttribute(flash_kernel, cudaFuncAttributeMaxDynamicSharedMemorySize, SMEM_BYTES);

    init_kernel<<<256, 256>>>(bb);
    combine_kernel<<<dim3(24, 16, 8), 256>>>(qkv, nemb, pemb, W);
    flash_kernel<<<dim3(T_LEN / QT, HH_TOT, 1 + NOBJ), 128, SMEM_BYTES>>>();
    finalize_kernel<<<dim3(T_LEN / 64, HH_TOT), 256>>>(out);
}

// round 14
// speedup vs baseline: 1.0110x; 1.0110x over previous
#include <cuda_runtime.h>
#include <math.h>

// Problem constants (fixed shapes from setup_inputs)
#define BS      4
#define NHEAD   8
#define HH_TOT  32          // BS*NHEAD
#define T_LEN   1024
#define CH      64
#define NOBJ    8

// flash tile config (v9: tf32 mma, single buffer 4 CTA/SM, P via warp-private smem)
#define QT      64          // q rows per block
#define KT      64          // k cols per tile
// smem (floats): QP[64][68] (Q staging, then P) | K[64][68] | V[64][72]
#define QP_OFF  0
#define KS_OFF  (64 * 68)                    // 4352
#define VS_OFF  (KS_OFF + 64 * 68)           // 8704
#define SMEM_FLOATS (VS_OFF + 64 * 72)       // 13312
#define SMEM_BYTES  (SMEM_FLOATS * 4)        // 53248

#define QSCALE  0.1803368801111204f          // 0.125 * log2(e): base-2 softmax domain

typedef unsigned long long ull;

// ---------------- helpers ----------------
__device__ __forceinline__ ull pk2(float lo, float hi) {
    ull r; asm("mov.b64 %0, {%1, %2};" : "=l"(r) : "f"(lo), "f"(hi)); return r;
}
__device__ __forceinline__ void upk2(ull v, float& lo, float& hi) {
    asm("mov.b64 {%0, %1}, %2;" : "=f"(lo), "=f"(hi) : "l"(v));
}
__device__ __forceinline__ ull fma2(ull a, ull b, ull c) {
    ull d; asm("fma.rn.f32x2 %0, %1, %2, %3;" : "=l"(d) : "l"(a), "l"(b), "l"(c)); return d;
}
__device__ __forceinline__ unsigned tf32r(float x) {
    unsigned u; asm("cvt.rna.tf32.f32 %0, %1;" : "=r"(u) : "f"(x)); return u;
}
__device__ __forceinline__ float tf32f(float x) {
    unsigned u = tf32r(x); return __uint_as_float(u);
}
__device__ __forceinline__ void cp16(unsigned dst, const void* src, int bytes) {
    asm volatile("cp.async.cg.shared.global [%0], [%1], 16, %2;"
                 :: "r"(dst), "l"(src), "r"(bytes));
}
#define CP_COMMIT() asm volatile("cp.async.commit_group;")
#define CP_WAIT0()  asm volatile("cp.async.wait_group 0;")

#define MMA_TF32(D, a0, a1, a2, a3, b0, b1)                                    \
    asm volatile(                                                              \
        "mma.sync.aligned.m16n8k8.row.col.f32.tf32.tf32.f32 "                  \
        "{%0,%1,%2,%3}, {%4,%5,%6,%7}, {%8,%9}, {%0,%1,%2,%3};"                \
        : "+f"((D)[0]), "+f"((D)[1]), "+f"((D)[2]), "+f"((D)[3])               \
        : "r"(a0), "r"(a1), "r"(a2), "r"(a3), "r"(b0), "r"(b1))

// ---------------- scratch (device globals; no allocs allowed) ----------------
__device__ float g_Qn[HH_TOT * T_LEN * CH];
__device__ float g_Kn[HH_TOT * T_LEN * CH];
__device__ float g_Vn[HH_TOT * T_LEN * CH];
__device__ float g_Qf[HH_TOT * T_LEN * CH];
__device__ float g_Kf[HH_TOT * T_LEN * CH];
__device__ float g_Vf[HH_TOT * T_LEN * CH];
__device__ float g_anull[HH_TOT * T_LEN * CH];
__device__ float g_afg[HH_TOT * T_LEN * CH];
__device__ int   g_regbox[BS * NOBJ * 4];   // i0,i1,j0,j1 (clamped to 32)
__device__ float g_cnt[BS * T_LEN];
__device__ int   g_nullskip[BS * 16];       // 1 if 64-token strip fully covered

// ---------------- init: zero a_fg; block 0 does bbox prep + counters + skip flags ----------------
__global__ __launch_bounds__(256)
void init_kernel(const float* __restrict__ bb) {
    const int tid = threadIdx.x;
    {
        float4* p = (float4*)g_afg;
        for (int i = blockIdx.x * 256 + tid; i < (HH_TOT * T_LEN * CH) / 4; i += 256 * 256)
            p[i] = make_float4(0.f, 0.f, 0.f, 0.f);
    }
    if (blockIdx.x != 0) return;
    __shared__ int sreg[BS * NOBJ][4];
    __shared__ float scnt[BS * T_LEN];
    if (tid < BS * NOBJ) {
        const float* p = bb + tid * 5;
        float x = p[0], y = p[1], w = p[2], h = p[3];
        int i0 = (int)fminf(31.0f, floorf(y * 32.0f));
        int j0 = (int)fminf(31.0f, floorf(x * 32.0f));
        int hh = (int)fmaxf(1.0f, ceilf(h * 32.0f));
        int ww = (int)fmaxf(1.0f, ceilf(w * 32.0f));
        int i1 = min(32, i0 + hh);
        int j1 = min(32, j0 + ww);
        g_regbox[tid * 4 + 0] = i0;  g_regbox[tid * 4 + 1] = i1;
        g_regbox[tid * 4 + 2] = j0;  g_regbox[tid * 4 + 3] = j1;
        sreg[tid][0] = i0; sreg[tid][1] = i1; sreg[tid][2] = j0; sreg[tid][3] = j1;
    }
    __syncthreads();
    for (int idx = tid; idx < BS * T_LEN; idx += 256) {
        int b = idx / T_LEN, t = idx % T_LEN;
        int i = t >> 5, j = t & 31;
        float c = 0.0f;
        #pragma unroll
        for (int o = 0; o < NOBJ; o++) {
            const int* r = sreg[b * NOBJ + o];
            if (i >= r[0] && i < r[1] && j >= r[2] && j < r[3]) c += 1.0f;
        }
        g_cnt[idx] = c;
        scnt[idx] = c;
    }
    __syncthreads();
    if (tid < BS * 16) {
        int b = tid >> 4, qb = tid & 15;
        int flag = 1;
        for (int k = 0; k < 64; k++)
            if (scnt[b * T_LEN + qb * 64 + k] < 0.5f) { flag = 0; break; }
        g_nullskip[tid] = flag;
    }
}

// ---------------- combine: qkv split + prompt projection GEMM (f32x2) ----------------
// Outputs tf32-pre-rounded; Q additionally scaled by log2(e) for base-2 softmax.
__global__ __launch_bounds__(256)
void combine_kernel(const float* __restrict__ qkv, const float* __restrict__ nemb,
                    const float* __restrict__ pemb, const float* __restrict__ W) {
    __shared__ float Ws[64 * 65];
    __shared__ __align__(16) float Es[64 * 68];
    const int g   = blockIdx.x;            // 0..23
    const int t0  = blockIdx.y * 64;
    const int zv  = blockIdx.z;
    const int b   = zv >> 1, var = zv & 1;
    const int head = g / 3, part = g % 3;
    const int cg0  = g * 64;
    const float* emb = (var ? pemb : nemb) + b * 64 * 1024;
    const int tid = threadIdx.x;

    for (int i = tid; i < 4096; i += 256) {
        int c = i >> 6, e = i & 63;
        Ws[c * 65 + e] = W[(cg0 + c) * 64 + e];
    }
    for (int i = tid; i < 4096; i += 256) {
        int e = i >> 6, t = i & 63;
        Es[e * 68 + t] = emb[e * 1024 + t0 + t];
    }
    __syncthreads();

    const int c = tid & 63, tg = tid >> 6;   // tg 0..3, 16 t each
    ull acc2[8];
    #pragma unroll
    for (int i = 0; i < 8; i++) acc2[i] = 0ULL;

    #pragma unroll 4
    for (int e = 0; e < 64; e++) {
        float w = Ws[c * 65 + e];
        ull w2 = pk2(w, w);
        const ull* row = (const ull*)(Es + e * 68 + tg * 16);
        #pragma unroll
        for (int k = 0; k < 8; k++) acc2[k] = fma2(w2, row[k], acc2[k]);
    }
    __syncthreads();
    const float* qk = qkv + (size_t)b * 1536 * 1024 + (size_t)cg0 * 1024 + t0;
    for (int i = tid; i < 4096; i += 256) {
        int cc = i >> 6, t = i & 63;
        Es[cc * 68 + t] = qk[cc * 1024 + t];
    }
    __syncthreads();

    float* dst;
    if (var == 0) dst = (part == 0 ? g_Qn : (part == 1 ? g_Kn : g_Vn));
    else          dst = (part == 0 ? g_Qf : (part == 1 ? g_Kf : g_Vf));
    dst += (b * NHEAD + head) * T_LEN * CH;
    const float sc = (part == 0) ? QSCALE : 1.0f;   // scale^2 * log2e folded into Q
    #pragma unroll
    for (int k = 0; k < 8; k++) {
        float a0, a1;
        upk2(acc2[k], a0, a1);
        int t = tg * 16 + 2 * k;
        dst[(t0 + t)     * CH + c] = tf32f((a0 + Es[c * 68 + t])     * sc);
        dst[(t0 + t + 1) * CH + c] = tf32f((a1 + Es[c * 68 + t + 1]) * sc);
    }
}

// ---------------- merged flash kernel: tf32 mma, P via warp-private smem ----------------
// z=0: null attention; z=1..8: fg object z-1 (region-restricted).
// 128 threads = 4 warps; warp w owns q-rows [16w, 16w+16).
// Q A-fragments hoisted to registers; its smem region is reused as the P buffer
// (warp-private rows -> __syncwarp ordering only, no extra block barriers).
__global__ __launch_bounds__(128, 4)
void flash_kernel() {
    extern __shared__ float sm[];
    const int z  = blockIdx.z;
    const int bh = blockIdx.y;
    const int qbase = blockIdx.x * QT;
    int i0 = 0, j00 = 0, rw = 32, nR = T_LEN;
    const float *Qp, *Kp, *Vp;
    if (z == 0) {
        if (g_nullskip[(bh >> 3) * 16 + blockIdx.x]) return;   // a_null unused here
        Qp = g_Qn + (size_t)bh * T_LEN * CH;
        Kp = g_Kn + (size_t)bh * T_LEN * CH;
        Vp = g_Vn + (size_t)bh * T_LEN * CH;
    } else {
        const int o = z - 1, b = bh >> 3;
        const int* box = g_regbox + (b * NOBJ + o) * 4;
        i0 = box[0]; j00 = box[2];
        rw = box[3] - j00;
        nR = (box[1] - i0) * rw;
        if (qbase >= nR) return;
        Qp = g_Qf + (size_t)bh * T_LEN * CH;
        Kp = g_Kf + (size_t)bh * T_LEN * CH;
        Vp = g_Vf + (size_t)bh * T_LEN * CH;
    }
    const int tid  = threadIdx.x;
    const int w    = tid >> 5, lane = tid & 31;
    const int la   = lane & 3, lg = lane >> 2;

    unsigned* QPu = (unsigned*)(sm + QP_OFF);
    const unsigned smem_u = (unsigned)__cvta_generic_to_shared(sm);

    // ---- issue Q + K0/V0 cp.asyncs together ----
    #pragma unroll
    for (int it = 0; it < 8; it++) {
        int idx = tid + it * 128;
        int r = idx >> 4, c4 = idx & 15;
        int u = qbase + r;
        const float* src = Qp;
        int bytes = 0;
        if (u < nR) {
            int t = (z == 0) ? u : ((i0 + u / rw) * 32 + j00 + u % rw);
            src = Qp + (size_t)t * CH + c4 * 4;
            bytes = 16;
        }
        cp16(smem_u + (QP_OFF + r * 68 + c4 * 4) * 4, src, bytes);
    }
    #pragma unroll
    for (int it = 0; it < 8; it++) {
        int idx = tid + it * 128;
        int s = idx >> 4, c4 = idx & 15;
        const float *ksrc = Kp, *vsrc = Vp;
        int bytes = 0;
        if (s < nR) {
            int t = (z == 0) ? s : ((i0 + s / rw) * 32 + j00 + s % rw);
            ksrc = Kp + (size_t)t * CH + c4 * 4;
            vsrc = Vp + (size_t)t * CH + c4 * 4;
            bytes = 16;
        }
        cp16(smem_u + (KS_OFF + s * 68 + c4 * 4) * 4, ksrc, bytes);
        cp16(smem_u + (VS_OFF + s * 72 + c4 * 4) * 4, vsrc, bytes);
    }
    CP_COMMIT();
    CP_WAIT0();
    __syncthreads();

    // ---- hoist Q fragments to registers; QP region becomes the P buffer ----
    unsigned qa[8][4];
    {
        const int aoff_lo = (16 * w + lg) * 68 + la;
        const int aoff_hi = aoff_lo + 8 * 68;
        #pragma unroll
        for (int ks = 0; ks < 8; ks++) {
            int kk = ks * 8;
            qa[ks][0] = QPu[aoff_lo + kk];
            qa[ks][1] = QPu[aoff_hi + kk];
            qa[ks][2] = QPu[aoff_lo + kk + 4];
            qa[ks][3] = QPu[aoff_hi + kk + 4];
        }
    }
    // (each warp only ever touches its own 16 QP rows from here on)

    float o[8][4];
    #pragma unroll
    for (int nt = 0; nt < 8; nt++) { o[nt][0] = o[nt][1] = o[nt][2] = o[nt][3] = 0.0f; }
    float m_lo = -1e30f, m_hi = -1e30f, l_lo = 0.0f, l_hi = 0.0f;

    const int boff  = lg * 68 + la;            // K B-frag base (banks 4lg+la)
    const int voff  = la * 72 + lg;            // V B-frag base (banks 8la+lg)
    const int prow_lo = (16 * w + lg) * 68;    // this thread's P rows
    const int prow_hi = prow_lo + 8 * 68;

    const int nkt = (nR + KT - 1) / KT;
    for (int kt = 0; kt < nkt; kt++) {
        if (kt > 0) {
            __syncthreads();                    // prior tile fully consumed
            #pragma unroll
            for (int it = 0; it < 8; it++) {
                int idx = tid + it * 128;
                int s = idx >> 4, c4 = idx & 15;
                int sg = kt * KT + s;
                const float *ksrc = Kp, *vsrc = Vp;
                int bytes = 0;
                if (sg < nR) {
                    int t = (z == 0) ? sg : ((i0 + sg / rw) * 32 + j00 + sg % rw);
                    ksrc = Kp + (size_t)t * CH + c4 * 4;
                    vsrc = Vp + (size_t)t * CH + c4 * 4;
                    bytes = 16;
                }
                cp16(smem_u + (KS_OFF + s * 68 + c4 * 4) * 4, ksrc, bytes);
                cp16(smem_u + (VS_OFF + s * 72 + c4 * 4) * 4, vsrc, bytes);
            }
            CP_COMMIT();
            CP_WAIT0();
            __syncthreads();
        }

        const unsigned* KsU = (const unsigned*)(sm + KS_OFF);
        const unsigned* VsU = (const unsigned*)(sm + VS_OFF);

        // ---- S = Q K^T via mma (base-2 domain) ----
        float acc[8][4];
        #pragma unroll
        for (int nt = 0; nt < 8; nt++) { acc[nt][0] = acc[nt][1] = acc[nt][2] = acc[nt][3] = 0.0f; }
        #pragma unroll
        for (int ks = 0; ks < 8; ks++) {
            int kk = ks * 8;
            #pragma unroll
            for (int nt = 0; nt < 8; nt++) {
                unsigned b0 = KsU[boff + nt * (8 * 68) + kk];
                unsigned b1 = KsU[boff + nt * (8 * 68) + kk + 4];
                MMA_TF32(acc[nt], qa[ks][0], qa[ks][1], qa[ks][2], qa[ks][3], b0, b1);
            }
        }

        // ---- mask columns beyond region (fg only) ----
        if (z != 0) {
            #pragma unroll
            for (int nt = 0; nt < 8; nt++) {
                int sc = kt * KT + 8 * nt + 2 * la;
                if (sc >= nR)     { acc[nt][0] = -1e30f; acc[nt][2] = -1e30f; }
                if (sc + 1 >= nR) { acc[nt][1] = -1e30f; acc[nt][3] = -1e30f; }
            }
        }

        // ---- online softmax, base-2 (rows lg / lg+8; reduce across quad lanes) ----
        float mx0 = -1e30f, mx1 = -1e30f;
        #pragma unroll
        for (int nt = 0; nt < 8; nt++) {
            mx0 = fmaxf(mx0, fmaxf(acc[nt][0], acc[nt][1]));
            mx1 = fmaxf(mx1, fmaxf(acc[nt][2], acc[nt][3]));
        }
        mx0 = fmaxf(mx0, __shfl_xor_sync(0xffffffffu, mx0, 1));
        mx0 = fmaxf(mx0, __shfl_xor_sync(0xffffffffu, mx0, 2));
        mx1 = fmaxf(mx1, __shfl_xor_sync(0xffffffffu, mx1, 1));
        mx1 = fmaxf(mx1, __shfl_xor_sync(0xffffffffu, mx1, 2));
        float mn0 = fmaxf(m_lo, mx0), mn1 = fmaxf(m_hi, mx1);
        float co0 = exp2f(m_lo - mn0), co1 = exp2f(m_hi - mn1);
        m_lo = mn0; m_hi = mn1;
        float rs0 = 0.0f, rs1 = 0.0f;
        #pragma unroll
        for (int nt = 0; nt < 8; nt++) {
            acc[nt][0] = exp2f(acc[nt][0] - mn0); rs0 += acc[nt][0];
            acc[nt][1] = exp2f(acc[nt][1] - mn0); rs0 += acc[nt][1];
            acc[nt][2] = exp2f(acc[nt][2] - mn1); rs1 += acc[nt][2];
            acc[nt][3] = exp2f(acc[nt][3] - mn1); rs1 += acc[nt][3];
        }
        rs0 += __shfl_xor_sync(0xffffffffu, rs0, 1);
        rs0 += __shfl_xor_sync(0xffffffffu, rs0, 2);
        rs1 += __shfl_xor_sync(0xffffffffu, rs1, 1);
        rs1 += __shfl_xor_sync(0xffffffffu, rs1, 2);
        l_lo = l_lo * co0 + rs0;
        l_hi = l_hi * co1 + rs1;
        #pragma unroll
        for (int nt = 0; nt < 8; nt++) {
            o[nt][0] *= co0; o[nt][1] *= co0;
            o[nt][2] *= co1; o[nt][3] *= co1;
        }

        // ---- stage P through warp-private smem rows (tf32-rounded) ----
        #pragma unroll
        for (int nt = 0; nt < 8; nt++) {
            int cc = 8 * nt + 2 * la;
            *(uint2*)(QPu + prow_lo + cc) = make_uint2(tf32r(acc[nt][0]), tf32r(acc[nt][1]));
            *(uint2*)(QPu + prow_hi + cc) = make_uint2(tf32r(acc[nt][2]), tf32r(acc[nt][3]));
        }
        __syncwarp();

        // ---- O += P V : A-frags from own P rows, B direct from row-major V ----
        #pragma unroll
        for (int ks = 0; ks < 8; ks++) {
            int kk = ks * 8;
            unsigned a0 = QPu[prow_lo + kk + la];
            unsigned a1 = QPu[prow_hi + kk + la];
            unsigned a2 = QPu[prow_lo + kk + la + 4];
            unsigned a3 = QPu[prow_hi + kk + la + 4];
            const unsigned* vb = VsU + voff + kk * 72;
            #pragma unroll
            for (int nt = 0; nt < 8; nt++) {
                unsigned b0 = vb[8 * nt];
                unsigned b1 = vb[8 * nt + 4 * 72];
                MMA_TF32(o[nt], a0, a1, a2, a3, b0, b1);
            }
        }
        __syncwarp();      // P reads done before next tile's softmax overwrites
    }

    // ---- epilogue ----
    float inv0 = 1.0f / l_lo, inv1 = 1.0f / l_hi;
    int u_lo = qbase + 16 * w + lg;
    int u_hi = u_lo + 8;
    if (z == 0) {
        float* Op = g_anull + (size_t)bh * T_LEN * CH;
        #pragma unroll
        for (int nt = 0; nt < 8; nt++) {
            int ch = 8 * nt + 2 * la;
            *(float2*)(Op + (size_t)u_lo * CH + ch) = make_float2(o[nt][0] * inv0, o[nt][1] * inv0);
            *(float2*)(Op + (size_t)u_hi * CH + ch) = make_float2(o[nt][2] * inv1, o[nt][3] * inv1);
        }
    } else {
        float* Ap = g_afg + (size_t)bh * T_LEN * CH;
        int t_lo = 0, t_hi = 0;
        if (u_lo < nR) t_lo = (i0 + u_lo / rw) * 32 + j00 + u_lo % rw;
        if (u_hi < nR) t_hi = (i0 + u_hi / rw) * 32 + j00 + u_hi % rw;
        #pragma unroll
        for (int nt = 0; nt < 8; nt++) {
            int ch = 8 * nt + 2 * la;
            if (u_lo < nR) {
                atomicAdd(Ap + (size_t)t_lo * CH + ch,     o[nt][0] * inv0);
                atomicAdd(Ap + (size_t)t_lo * CH + ch + 1, o[nt][1] * inv0);
            }
            if (u_hi < nR) {
                atomicAdd(Ap + (size_t)t_hi * CH + ch,     o[nt][2] * inv1);
                atomicAdd(Ap + (size_t)t_hi * CH + ch + 1, o[nt][3] * inv1);
            }
        }
    }
}

// ---------------- finalize: select + divide + transpose to (bs, 512, T) ----------------
__global__ __launch_bounds__(256)
void finalize_kernel(float* __restrict__ out) {
    __shared__ float smf[64 * 65];
    const int bh = blockIdx.y;
    const int t0 = blockIdx.x * 64;
    const int b = bh >> 3, h = bh & 7;
    const float* An = g_anull + (size_t)bh * T_LEN * CH;
    const float* Af = g_afg   + (size_t)bh * T_LEN * CH;
    const float* Cn = g_cnt + b * T_LEN;
    const int tid = threadIdx.x;
    for (int i = tid; i < 4096; i += 256) {
        int tt = i >> 6, c = i & 63;
        int t = t0 + tt;
        float cnt = Cn[t];
        float v = (cnt > 0.5f) ? Af[(size_t)t * CH + c] / cnt : An[(size_t)t * CH + c];
        smf[tt * 65 + c] = v;
    }
    __syncthreads();
    float* op = out + (size_t)b * 512 * 1024 + (size_t)h * 64 * 1024 + t0;
    for (int i = tid; i < 4096; i += 256) {
        int c = i >> 6, tt = i & 63;
        op[(size_t)c * 1024 + tt] = smf[tt * 65 + c];
    }
}

// ---------------- launch ----------------
extern "C" void kernel_launch(void* const* d_in, const int* in_sizes, int n_in,
                              void* d_out, int out_size) {
    const float* qkv  = (const float*)d_in[0];
    const float* bb   = (const float*)d_in[1];
    const float* nemb = (const float*)d_in[2];
    const float* pemb = (const float*)d_in[3];
    const float* W    = (const float*)d_in[4];
    float* out = (float*)d_out;

    cudaFuncSetAttribute(flash_kernel, cudaFuncAttributeMaxDynamicSharedMemorySize, SMEM_BYTES);

    init_kernel<<<256, 256>>>(bb);
    combine_kernel<<<dim3(24, 16, 8), 256>>>(qkv, nemb, pemb, W);
    flash_kernel<<<dim3(T_LEN / QT, HH_TOT, 1 + NOBJ), 128, SMEM_BYTES>>>();
    finalize_kernel<<<dim3(T_LEN / 64, HH_TOT), 256>>>(out);
}

// round 15
// speedup vs baseline: 1.1488x; 1.1363x over previous
#include <cuda_runtime.h>
#include <math.h>

// Problem constants (fixed shapes from setup_inputs)
#define BS      4
#define NHEAD   8
#define HH_TOT  32          // BS*NHEAD
#define T_LEN   1024
#define CH      64
#define NOBJ    8

// flash tile config (v10: tf32 mma, compacted null q-rows)
#define QT      64          // q rows per block
#define KT      64          // k cols per tile
// smem (floats): QP[64][68] (Q staging, then P) | K[64][68] | V[64][72]
#define QP_OFF  0
#define KS_OFF  (64 * 68)                    // 4352
#define VS_OFF  (KS_OFF + 64 * 68)           // 8704
#define SMEM_FLOATS (VS_OFF + 64 * 72)       // 13312
#define SMEM_BYTES  (SMEM_FLOATS * 4)        // 53248

#define QSCALE  0.1803368801111204f          // 0.125 * log2(e): base-2 softmax domain

typedef unsigned long long ull;

// ---------------- helpers ----------------
__device__ __forceinline__ ull pk2(float lo, float hi) {
    ull r; asm("mov.b64 %0, {%1, %2};" : "=l"(r) : "f"(lo), "f"(hi)); return r;
}
__device__ __forceinline__ void upk2(ull v, float& lo, float& hi) {
    asm("mov.b64 {%0, %1}, %2;" : "=f"(lo), "=f"(hi) : "l"(v));
}
__device__ __forceinline__ ull fma2(ull a, ull b, ull c) {
    ull d; asm("fma.rn.f32x2 %0, %1, %2, %3;" : "=l"(d) : "l"(a), "l"(b), "l"(c)); return d;
}
__device__ __forceinline__ unsigned tf32r(float x) {
    unsigned u; asm("cvt.rna.tf32.f32 %0, %1;" : "=r"(u) : "f"(x)); return u;
}
__device__ __forceinline__ float tf32f(float x) {
    unsigned u = tf32r(x); return __uint_as_float(u);
}
__device__ __forceinline__ void cp16(unsigned dst, const void* src, int bytes) {
    asm volatile("cp.async.cg.shared.global [%0], [%1], 16, %2;"
                 :: "r"(dst), "l"(src), "r"(bytes));
}
#define CP_COMMIT() asm volatile("cp.async.commit_group;")
#define CP_WAIT0()  asm volatile("cp.async.wait_group 0;")

#define MMA_TF32(D, a0, a1, a2, a3, b0, b1)                                    \
    asm volatile(                                                              \
        "mma.sync.aligned.m16n8k8.row.col.f32.tf32.tf32.f32 "                  \
        "{%0,%1,%2,%3}, {%4,%5,%6,%7}, {%8,%9}, {%0,%1,%2,%3};"                \
        : "+f"((D)[0]), "+f"((D)[1]), "+f"((D)[2]), "+f"((D)[3])               \
        : "r"(a0), "r"(a1), "r"(a2), "r"(a3), "r"(b0), "r"(b1))

// ---------------- scratch (device globals; no allocs allowed) ----------------
__device__ float g_Qn[HH_TOT * T_LEN * CH];
__device__ float g_Kn[HH_TOT * T_LEN * CH];
__device__ float g_Vn[HH_TOT * T_LEN * CH];
__device__ float g_Qf[HH_TOT * T_LEN * CH];
__device__ float g_Kf[HH_TOT * T_LEN * CH];
__device__ float g_Vf[HH_TOT * T_LEN * CH];
__device__ float g_anull[HH_TOT * T_LEN * CH];
__device__ float g_afg[HH_TOT * T_LEN * CH];
__device__ int   g_regbox[BS * NOBJ * 4];   // i0,i1,j0,j1 (clamped to 32)
__device__ float g_cnt[BS * T_LEN];
__device__ int   g_uncidx[BS * T_LEN];      // compacted uncovered-token indices per batch
__device__ int   g_unccnt[BS];              // count of uncovered tokens per batch

// ---------------- init: zero a_fg; block 0: bbox prep + counters + compaction ----------------
__global__ __launch_bounds__(256)
void init_kernel(const float* __restrict__ bb) {
    const int tid = threadIdx.x;
    {
        float4* p = (float4*)g_afg;
        for (int i = blockIdx.x * 256 + tid; i < (HH_TOT * T_LEN * CH) / 4; i += 256 * 256)
            p[i] = make_float4(0.f, 0.f, 0.f, 0.f);
    }
    if (blockIdx.x != 0) return;
    __shared__ int sreg[BS * NOBJ][4];
    __shared__ float scnt[BS * T_LEN];
    if (tid < BS * NOBJ) {
        const float* p = bb + tid * 5;
        float x = p[0], y = p[1], w = p[2], h = p[3];
        int i0 = (int)fminf(31.0f, floorf(y * 32.0f));
        int j0 = (int)fminf(31.0f, floorf(x * 32.0f));
        int hh = (int)fmaxf(1.0f, ceilf(h * 32.0f));
        int ww = (int)fmaxf(1.0f, ceilf(w * 32.0f));
        int i1 = min(32, i0 + hh);
        int j1 = min(32, j0 + ww);
        g_regbox[tid * 4 + 0] = i0;  g_regbox[tid * 4 + 1] = i1;
        g_regbox[tid * 4 + 2] = j0;  g_regbox[tid * 4 + 3] = j1;
        sreg[tid][0] = i0; sreg[tid][1] = i1; sreg[tid][2] = j0; sreg[tid][3] = j1;
    }
    __syncthreads();
    for (int idx = tid; idx < BS * T_LEN; idx += 256) {
        int b = idx / T_LEN, t = idx % T_LEN;
        int i = t >> 5, j = t & 31;
        float c = 0.0f;
        #pragma unroll
        for (int o = 0; o < NOBJ; o++) {
            const int* r = sreg[b * NOBJ + o];
            if (i >= r[0] && i < r[1] && j >= r[2] && j < r[3]) c += 1.0f;
        }
        g_cnt[idx] = c;
        scnt[idx] = c;
    }
    __syncthreads();
    // warp w (< BS) compacts uncovered tokens of batch w (order-preserving)
    const int wid = tid >> 5, lane = tid & 31;
    if (wid < BS) {
        int base = 0;
        for (int c0 = 0; c0 < T_LEN; c0 += 32) {
            int t = c0 + lane;
            bool unc = scnt[wid * T_LEN + t] < 0.5f;
            unsigned mask = __ballot_sync(0xffffffffu, unc);
            int pos = base + __popc(mask & ((1u << lane) - 1u));
            if (unc) g_uncidx[wid * T_LEN + pos] = t;
            base += __popc(mask);
        }
        if (lane == 0) g_unccnt[wid] = base;
    }
}

// ---------------- combine: qkv split + prompt projection GEMM (f32x2) ----------------
// Outputs tf32-pre-rounded; Q additionally scaled by log2(e) for base-2 softmax.
__global__ __launch_bounds__(256)
void combine_kernel(const float* __restrict__ qkv, const float* __restrict__ nemb,
                    const float* __restrict__ pemb, const float* __restrict__ W) {
    __shared__ float Ws[64 * 65];
    __shared__ __align__(16) float Es[64 * 68];
    const int g   = blockIdx.x;            // 0..23
    const int t0  = blockIdx.y * 64;
    const int zv  = blockIdx.z;
    const int b   = zv >> 1, var = zv & 1;
    const int head = g / 3, part = g % 3;
    const int cg0  = g * 64;
    const float* emb = (var ? pemb : nemb) + b * 64 * 1024;
    const int tid = threadIdx.x;

    for (int i = tid; i < 4096; i += 256) {
        int c = i >> 6, e = i & 63;
        Ws[c * 65 + e] = W[(cg0 + c) * 64 + e];
    }
    for (int i = tid; i < 4096; i += 256) {
        int e = i >> 6, t = i & 63;
        Es[e * 68 + t] = emb[e * 1024 + t0 + t];
    }
    __syncthreads();

    const int c = tid & 63, tg = tid >> 6;   // tg 0..3, 16 t each
    ull acc2[8];
    #pragma unroll
    for (int i = 0; i < 8; i++) acc2[i] = 0ULL;

    #pragma unroll 4
    for (int e = 0; e < 64; e++) {
        float w = Ws[c * 65 + e];
        ull w2 = pk2(w, w);
        const ull* row = (const ull*)(Es + e * 68 + tg * 16);
        #pragma unroll
        for (int k = 0; k < 8; k++) acc2[k] = fma2(w2, row[k], acc2[k]);
    }
    __syncthreads();
    const float* qk = qkv + (size_t)b * 1536 * 1024 + (size_t)cg0 * 1024 + t0;
    for (int i = tid; i < 4096; i += 256) {
        int cc = i >> 6, t = i & 63;
        Es[cc * 68 + t] = qk[cc * 1024 + t];
    }
    __syncthreads();

    float* dst;
    if (var == 0) dst = (part == 0 ? g_Qn : (part == 1 ? g_Kn : g_Vn));
    else          dst = (part == 0 ? g_Qf : (part == 1 ? g_Kf : g_Vf));
    dst += (b * NHEAD + head) * T_LEN * CH;
    const float sc = (part == 0) ? QSCALE : 1.0f;   // scale^2 * log2e folded into Q
    #pragma unroll
    for (int k = 0; k < 8; k++) {
        float a0, a1;
        upk2(acc2[k], a0, a1);
        int t = tg * 16 + 2 * k;
        dst[(t0 + t)     * CH + c] = tf32f((a0 + Es[c * 68 + t])     * sc);
        dst[(t0 + t + 1) * CH + c] = tf32f((a1 + Es[c * 68 + t + 1]) * sc);
    }
}

// ---------------- merged flash kernel: tf32 mma, compacted null rows ----------------
// z=0: null attention over UNCOVERED tokens only (gather via g_uncidx, full K);
// z=1..8: fg object z-1 (region-restricted rows AND cols).
// 128 threads = 4 warps; warp w owns q-rows [16w, 16w+16).
__global__ __launch_bounds__(128, 4)
void flash_kernel() {
    extern __shared__ float sm[];
    const int z  = blockIdx.z;
    const int bh = blockIdx.y;
    const int qbase = blockIdx.x * QT;
    int i0 = 0, j00 = 0, rw = 32;
    int nR = T_LEN;          // k-side extent
    int nQ;                  // q-side extent
    const int* idxp = 0;
    const float *Qp, *Kp, *Vp;
    if (z == 0) {
        const int b = bh >> 3;
        nQ = g_unccnt[b];
        if (qbase >= nQ) return;
        idxp = g_uncidx + b * T_LEN;
        Qp = g_Qn + (size_t)bh * T_LEN * CH;
        Kp = g_Kn + (size_t)bh * T_LEN * CH;
        Vp = g_Vn + (size_t)bh * T_LEN * CH;
    } else {
        const int o = z - 1, b = bh >> 3;
        const int* box = g_regbox + (b * NOBJ + o) * 4;
        i0 = box[0]; j00 = box[2];
        rw = box[3] - j00;
        nR = (box[1] - i0) * rw;
        nQ = nR;
        if (qbase >= nQ) return;
        Qp = g_Qf + (size_t)bh * T_LEN * CH;
        Kp = g_Kf + (size_t)bh * T_LEN * CH;
        Vp = g_Vf + (size_t)bh * T_LEN * CH;
    }
    const int tid  = threadIdx.x;
    const int w    = tid >> 5, lane = tid & 31;
    const int la   = lane & 3, lg = lane >> 2;

    unsigned* QPu = (unsigned*)(sm + QP_OFF);
    const unsigned smem_u = (unsigned)__cvta_generic_to_shared(sm);

    // ---- issue Q + K0/V0 cp.asyncs together ----
    #pragma unroll
    for (int it = 0; it < 8; it++) {
        int idx = tid + it * 128;
        int r = idx >> 4, c4 = idx & 15;
        int u = qbase + r;
        const float* src = Qp;
        int bytes = 0;
        if (u < nQ) {
            int t = (z == 0) ? idxp[u] : ((i0 + u / rw) * 32 + j00 + u % rw);
            src = Qp + (size_t)t * CH + c4 * 4;
            bytes = 16;
        }
        cp16(smem_u + (QP_OFF + r * 68 + c4 * 4) * 4, src, bytes);
    }
    #pragma unroll
    for (int it = 0; it < 8; it++) {
        int idx = tid + it * 128;
        int s = idx >> 4, c4 = idx & 15;
        const float *ksrc = Kp, *vsrc = Vp;
        int bytes = 0;
        if (s < nR) {
            int t = (z == 0) ? s : ((i0 + s / rw) * 32 + j00 + s % rw);
            ksrc = Kp + (size_t)t * CH + c4 * 4;
            vsrc = Vp + (size_t)t * CH + c4 * 4;
            bytes = 16;
        }
        cp16(smem_u + (KS_OFF + s * 68 + c4 * 4) * 4, ksrc, bytes);
        cp16(smem_u + (VS_OFF + s * 72 + c4 * 4) * 4, vsrc, bytes);
    }
    CP_COMMIT();
    CP_WAIT0();
    __syncthreads();

    // ---- hoist Q fragments to registers; QP region becomes the P buffer ----
    unsigned qa[8][4];
    {
        const int aoff_lo = (16 * w + lg) * 68 + la;
        const int aoff_hi = aoff_lo + 8 * 68;
        #pragma unroll
        for (int ks = 0; ks < 8; ks++) {
            int kk = ks * 8;
            qa[ks][0] = QPu[aoff_lo + kk];
            qa[ks][1] = QPu[aoff_hi + kk];
            qa[ks][2] = QPu[aoff_lo + kk + 4];
            qa[ks][3] = QPu[aoff_hi + kk + 4];
        }
    }
    // (each warp only ever touches its own 16 QP rows from here on)

    float o[8][4];
    #pragma unroll
    for (int nt = 0; nt < 8; nt++) { o[nt][0] = o[nt][1] = o[nt][2] = o[nt][3] = 0.0f; }
    float m_lo = -1e30f, m_hi = -1e30f, l_lo = 0.0f, l_hi = 0.0f;

    const int boff  = lg * 68 + la;            // K B-frag base (banks 4lg+la)
    const int voff  = la * 72 + lg;            // V B-frag base (banks 8la+lg)
    const int prow_lo = (16 * w + lg) * 68;    // this thread's P rows
    const int prow_hi = prow_lo + 8 * 68;

    const int nkt = (nR + KT - 1) / KT;
    for (int kt = 0; kt < nkt; kt++) {
        if (kt > 0) {
            __syncthreads();                    // prior tile fully consumed
            #pragma unroll
            for (int it = 0; it < 8; it++) {
                int idx = tid + it * 128;
                int s = idx >> 4, c4 = idx & 15;
                int sg = kt * KT + s;
                const float *ksrc = Kp, *vsrc = Vp;
                int bytes = 0;
                if (sg < nR) {
                    int t = (z == 0) ? sg : ((i0 + sg / rw) * 32 + j00 + sg % rw);
                    ksrc = Kp + (size_t)t * CH + c4 * 4;
                    vsrc = Vp + (size_t)t * CH + c4 * 4;
                    bytes = 16;
                }
                cp16(smem_u + (KS_OFF + s * 68 + c4 * 4) * 4, ksrc, bytes);
                cp16(smem_u + (VS_OFF + s * 72 + c4 * 4) * 4, vsrc, bytes);
            }
            CP_COMMIT();
            CP_WAIT0();
            __syncthreads();
        }

        const unsigned* KsU = (const unsigned*)(sm + KS_OFF);
        const unsigned* VsU = (const unsigned*)(sm + VS_OFF);

        // ---- S = Q K^T via mma (base-2 domain) ----
        float acc[8][4];
        #pragma unroll
        for (int nt = 0; nt < 8; nt++) { acc[nt][0] = acc[nt][1] = acc[nt][2] = acc[nt][3] = 0.0f; }
        #pragma unroll
        for (int ks = 0; ks < 8; ks++) {
            int kk = ks * 8;
            #pragma unroll
            for (int nt = 0; nt < 8; nt++) {
                unsigned b0 = KsU[boff + nt * (8 * 68) + kk];
                unsigned b1 = KsU[boff + nt * (8 * 68) + kk + 4];
                MMA_TF32(acc[nt], qa[ks][0], qa[ks][1], qa[ks][2], qa[ks][3], b0, b1);
            }
        }

        // ---- mask columns beyond region (fg only) ----
        if (z != 0) {
            #pragma unroll
            for (int nt = 0; nt < 8; nt++) {
                int sc = kt * KT + 8 * nt + 2 * la;
                if (sc >= nR)     { acc[nt][0] = -1e30f; acc[nt][2] = -1e30f; }
                if (sc + 1 >= nR) { acc[nt][1] = -1e30f; acc[nt][3] = -1e30f; }
            }
        }

        // ---- online softmax, base-2 (rows lg / lg+8; reduce across quad lanes) ----
        float mx0 = -1e30f, mx1 = -1e30f;
        #pragma unroll
        for (int nt = 0; nt < 8; nt++) {
            mx0 = fmaxf(mx0, fmaxf(acc[nt][0], acc[nt][1]));
            mx1 = fmaxf(mx1, fmaxf(acc[nt][2], acc[nt][3]));
        }
        mx0 = fmaxf(mx0, __shfl_xor_sync(0xffffffffu, mx0, 1));
        mx0 = fmaxf(mx0, __shfl_xor_sync(0xffffffffu, mx0, 2));
        mx1 = fmaxf(mx1, __shfl_xor_sync(0xffffffffu, mx1, 1));
        mx1 = fmaxf(mx1, __shfl_xor_sync(0xffffffffu, mx1, 2));
        float mn0 = fmaxf(m_lo, mx0), mn1 = fmaxf(m_hi, mx1);
        float co0 = exp2f(m_lo - mn0), co1 = exp2f(m_hi - mn1);
        m_lo = mn0; m_hi = mn1;
        float rs0 = 0.0f, rs1 = 0.0f;
        #pragma unroll
        for (int nt = 0; nt < 8; nt++) {
            acc[nt][0] = exp2f(acc[nt][0] - mn0); rs0 += acc[nt][0];
            acc[nt][1] = exp2f(acc[nt][1] - mn0); rs0 += acc[nt][1];
            acc[nt][2] = exp2f(acc[nt][2] - mn1); rs1 += acc[nt][2];
            acc[nt][3] = exp2f(acc[nt][3] - mn1); rs1 += acc[nt][3];
        }
        rs0 += __shfl_xor_sync(0xffffffffu, rs0, 1);
        rs0 += __shfl_xor_sync(0xffffffffu, rs0, 2);
        rs1 += __shfl_xor_sync(0xffffffffu, rs1, 1);
        rs1 += __shfl_xor_sync(0xffffffffu, rs1, 2);
        l_lo = l_lo * co0 + rs0;
        l_hi = l_hi * co1 + rs1;
        #pragma unroll
        for (int nt = 0; nt < 8; nt++) {
            o[nt][0] *= co0; o[nt][1] *= co0;
            o[nt][2] *= co1; o[nt][3] *= co1;
        }

        // ---- stage P through warp-private smem rows (tf32-rounded) ----
        #pragma unroll
        for (int nt = 0; nt < 8; nt++) {
            int cc = 8 * nt + 2 * la;
            *(uint2*)(QPu + prow_lo + cc) = make_uint2(tf32r(acc[nt][0]), tf32r(acc[nt][1]));
            *(uint2*)(QPu + prow_hi + cc) = make_uint2(tf32r(acc[nt][2]), tf32r(acc[nt][3]));
        }
        __syncwarp();

        // ---- O += P V : A-frags from own P rows, B direct from row-major V ----
        #pragma unroll
        for (int ks = 0; ks < 8; ks++) {
            int kk = ks * 8;
            unsigned a0 = QPu[prow_lo + kk + la];
            unsigned a1 = QPu[prow_hi + kk + la];
            unsigned a2 = QPu[prow_lo + kk + la + 4];
            unsigned a3 = QPu[prow_hi + kk + la + 4];
            const unsigned* vb = VsU + voff + kk * 72;
            #pragma unroll
            for (int nt = 0; nt < 8; nt++) {
                unsigned b0 = vb[8 * nt];
                unsigned b1 = vb[8 * nt + 4 * 72];
                MMA_TF32(o[nt], a0, a1, a2, a3, b0, b1);
            }
        }
        __syncwarp();      // P reads done before next tile's softmax overwrites
    }

    // ---- epilogue ----
    float inv0 = 1.0f / l_lo, inv1 = 1.0f / l_hi;
    int u_lo = qbase + 16 * w + lg;
    int u_hi = u_lo + 8;
    if (z == 0) {
        float* Op = g_anull + (size_t)bh * T_LEN * CH;
        int t_lo = 0, t_hi = 0;
        if (u_lo < nQ) t_lo = idxp[u_lo];
        if (u_hi < nQ) t_hi = idxp[u_hi];
        #pragma unroll
        for (int nt = 0; nt < 8; nt++) {
            int ch = 8 * nt + 2 * la;
            if (u_lo < nQ)
                *(float2*)(Op + (size_t)t_lo * CH + ch) = make_float2(o[nt][0] * inv0, o[nt][1] * inv0);
            if (u_hi < nQ)
                *(float2*)(Op + (size_t)t_hi * CH + ch) = make_float2(o[nt][2] * inv1, o[nt][3] * inv1);
        }
    } else {
        float* Ap = g_afg + (size_t)bh * T_LEN * CH;
        int t_lo = 0, t_hi = 0;
        if (u_lo < nQ) t_lo = (i0 + u_lo / rw) * 32 + j00 + u_lo % rw;
        if (u_hi < nQ) t_hi = (i0 + u_hi / rw) * 32 + j00 + u_hi % rw;
        #pragma unroll
        for (int nt = 0; nt < 8; nt++) {
            int ch = 8 * nt + 2 * la;
            if (u_lo < nQ) {
                atomicAdd(Ap + (size_t)t_lo * CH + ch,     o[nt][0] * inv0);
                atomicAdd(Ap + (size_t)t_lo * CH + ch + 1, o[nt][1] * inv0);
            }
            if (u_hi < nQ) {
                atomicAdd(Ap + (size_t)t_hi * CH + ch,     o[nt][2] * inv1);
                atomicAdd(Ap + (size_t)t_hi * CH + ch + 1, o[nt][3] * inv1);
            }
        }
    }
}

// ---------------- finalize: select + divide + transpose to (bs, 512, T) ----------------
__global__ __launch_bounds__(256)
void finalize_kernel(float* __restrict__ out) {
    __shared__ float smf[64 * 65];
    const int bh = blockIdx.y;
    const int t0 = blockIdx.x * 64;
    const int b = bh >> 3, h = bh & 7;
    const float* An = g_anull + (size_t)bh * T_LEN * CH;
    const float* Af = g_afg   + (size_t)bh * T_LEN * CH;
    const float* Cn = g_cnt + b * T_LEN;
    const int tid = threadIdx.x;
    for (int i = tid; i < 4096; i += 256) {
        int tt = i >> 6, c = i & 63;
        int t = t0 + tt;
        float cnt = Cn[t];
        float v = (cnt > 0.5f) ? Af[(size_t)t * CH + c] / cnt : An[(size_t)t * CH + c];
        smf[tt * 65 + c] = v;
    }
    __syncthreads();
    float* op = out + (size_t)b * 512 * 1024 + (size_t)h * 64 * 1024 + t0;
    for (int i = tid; i < 4096; i += 256) {
        int c = i >> 6, tt = i & 63;
        op[(size_t)c * 1024 + tt] = smf[tt * 65 + c];
    }
}

// ---------------- launch ----------------
extern "C" void kernel_launch(void* const* d_in, const int* in_sizes, int n_in,
                              void* d_out, int out_size) {
    const float* qkv  = (const float*)d_in[0];
    const float* bb   = (const float*)d_in[1];
    const float* nemb = (const float*)d_in[2];
    const float* pemb = (const float*)d_in[3];
    const float* W    = (const float*)d_in[4];
    float* out = (float*)d_out;

    cudaFuncSetAttribute(flash_kernel, cudaFuncAttributeMaxDynamicSharedMemorySize, SMEM_BYTES);

    init_kernel<<<256, 256>>>(bb);
    combine_kernel<<<dim3(24, 16, 8), 256>>>(qkv, nemb, pemb, W);
    flash_kernel<<<dim3(T_LEN / QT, HH_TOT, 1 + NOBJ), 128, SMEM_BYTES>>>();
    finalize_kernel<<<dim3(T_LEN / 64, HH_TOT), 256>>>(out);
}

// round 17
// speedup vs baseline: 1.6267x; 1.4160x over previous
#include <cuda_runtime.h>
#include <cuda_fp16.h>
#include <math.h>

// Problem constants (fixed shapes from setup_inputs)
#define BS      4
#define NHEAD   8
#define HH_TOT  32          // BS*NHEAD
#define T_LEN   1024
#define CH      64
#define NOBJ    8

// flash tile config (v11b: fp16 m16n8k16 mma, ldmatrix.trans V, compacted null rows)
#define QT      64          // q rows per block
#define KT      64          // k cols per tile
// smem byte offsets: QP (Q staging then P, 64 rows x 72 halves = 144B pitch)
//                    K  (64 x 144B) | V (64 x 144B)  -- all cp.async dsts 16B-aligned
#define QP_B    0
#define KS_B    9216
#define VS_B    18432
#define SMEM_BYTES 27648

#define QSCALE  0.1803368801111204f          // 0.125 * log2(e): base-2 softmax domain

typedef unsigned long long ull;

// ---------------- helpers ----------------
__device__ __forceinline__ ull pk2(float lo, float hi) {
    ull r; asm("mov.b64 %0, {%1, %2};" : "=l"(r) : "f"(lo), "f"(hi)); return r;
}
__device__ __forceinline__ void upk2(ull v, float& lo, float& hi) {
    asm("mov.b64 {%0, %1}, %2;" : "=f"(lo), "=f"(hi) : "l"(v));
}
__device__ __forceinline__ ull fma2(ull a, ull b, ull c) {
    ull d; asm("fma.rn.f32x2 %0, %1, %2, %3;" : "=l"(d) : "l"(a), "l"(b), "l"(c)); return d;
}
__device__ __forceinline__ void cp16(unsigned dst, const void* src, int bytes) {
    asm volatile("cp.async.cg.shared.global [%0], [%1], 16, %2;"
                 :: "r"(dst), "l"(src), "r"(bytes));
}
#define CP_COMMIT() asm volatile("cp.async.commit_group;")
#define CP_WAIT0()  asm volatile("cp.async.wait_group 0;")

// fp16 mma: D(f32) += A(f16) * B(f16), 16x8x16
#define MMA_F16(D, a0, a1, a2, a3, b0, b1)                                     \
    asm volatile(                                                              \
        "mma.sync.aligned.m16n8k16.row.col.f32.f16.f16.f32 "                   \
        "{%0,%1,%2,%3}, {%4,%5,%6,%7}, {%8,%9}, {%0,%1,%2,%3};"                \
        : "+f"((D)[0]), "+f"((D)[1]), "+f"((D)[2]), "+f"((D)[3])               \
        : "r"(a0), "r"(a1), "r"(a2), "r"(a3), "r"(b0), "r"(b1))

#define LDSM_X2_T(r0, r1, addr)                                                \
    asm volatile("ldmatrix.sync.aligned.m8n8.x2.trans.shared.b16 {%0,%1}, [%2];" \
                 : "=r"(r0), "=r"(r1) : "r"(addr))

// ---------------- scratch (device globals; no allocs allowed) ----------------
__device__ __half g_Qn[HH_TOT * T_LEN * CH];
__device__ __half g_Kn[HH_TOT * T_LEN * CH];
__device__ __half g_Vn[HH_TOT * T_LEN * CH];
__device__ __half g_Qf[HH_TOT * T_LEN * CH];
__device__ __half g_Kf[HH_TOT * T_LEN * CH];
__device__ __half g_Vf[HH_TOT * T_LEN * CH];
__device__ float g_anull[HH_TOT * T_LEN * CH];
__device__ float g_afg[HH_TOT * T_LEN * CH];
__device__ int   g_regbox[BS * NOBJ * 4];   // i0,i1,j0,j1 (clamped to 32)
__device__ float g_cnt[BS * T_LEN];
__device__ int   g_uncidx[BS * T_LEN];      // compacted uncovered-token indices per batch
__device__ int   g_unccnt[BS];              // count of uncovered tokens per batch

// ---------------- init: zero a_fg; block 0: bbox prep + counters + compaction ----------------
__global__ __launch_bounds__(256)
void init_kernel(const float* __restrict__ bb) {
    const int tid = threadIdx.x;
    {
        float4* p = (float4*)g_afg;
        for (int i = blockIdx.x * 256 + tid; i < (HH_TOT * T_LEN * CH) / 4; i += 256 * 256)
            p[i] = make_float4(0.f, 0.f, 0.f, 0.f);
    }
    if (blockIdx.x != 0) return;
    __shared__ int sreg[BS * NOBJ][4];
    __shared__ float scnt[BS * T_LEN];
    if (tid < BS * NOBJ) {
        const float* p = bb + tid * 5;
        float x = p[0], y = p[1], w = p[2], h = p[3];
        int i0 = (int)fminf(31.0f, floorf(y * 32.0f));
        int j0 = (int)fminf(31.0f, floorf(x * 32.0f));
        int hh = (int)fmaxf(1.0f, ceilf(h * 32.0f));
        int ww = (int)fmaxf(1.0f, ceilf(w * 32.0f));
        int i1 = min(32, i0 + hh);
        int j1 = min(32, j0 + ww);
        g_regbox[tid * 4 + 0] = i0;  g_regbox[tid * 4 + 1] = i1;
        g_regbox[tid * 4 + 2] = j0;  g_regbox[tid * 4 + 3] = j1;
        sreg[tid][0] = i0; sreg[tid][1] = i1; sreg[tid][2] = j0; sreg[tid][3] = j1;
    }
    __syncthreads();
    for (int idx = tid; idx < BS * T_LEN; idx += 256) {
        int b = idx / T_LEN, t = idx % T_LEN;
        int i = t >> 5, j = t & 31;
        float c = 0.0f;
        #pragma unroll
        for (int o = 0; o < NOBJ; o++) {
            const int* r = sreg[b * NOBJ + o];
            if (i >= r[0] && i < r[1] && j >= r[2] && j < r[3]) c += 1.0f;
        }
        g_cnt[idx] = c;
        scnt[idx] = c;
    }
    __syncthreads();
    // warp w (< BS) compacts uncovered tokens of batch w (order-preserving)
    const int wid = tid >> 5, lane = tid & 31;
    if (wid < BS) {
        int base = 0;
        for (int c0 = 0; c0 < T_LEN; c0 += 32) {
            int t = c0 + lane;
            bool unc = scnt[wid * T_LEN + t] < 0.5f;
            unsigned mask = __ballot_sync(0xffffffffu, unc);
            int pos = base + __popc(mask & ((1u << lane) - 1u));
            if (unc) g_uncidx[wid * T_LEN + pos] = t;
            base += __popc(mask);
        }
        if (lane == 0) g_unccnt[wid] = base;
    }
}

// ---------------- combine: qkv split + prompt projection GEMM (f32x2, half output) ----------------
// Outputs fp16; Q additionally scaled by log2(e) for base-2 softmax.
__global__ __launch_bounds__(256)
void combine_kernel(const float* __restrict__ qkv, const float* __restrict__ nemb,
                    const float* __restrict__ pemb, const float* __restrict__ W) {
    __shared__ float Ws[64 * 65];
    __shared__ __align__(16) float Es[64 * 68];
    const int g   = blockIdx.x;            // 0..23
    const int t0  = blockIdx.y * 64;
    const int zv  = blockIdx.z;
    const int b   = zv >> 1, var = zv & 1;
    const int head = g / 3, part = g % 3;
    const int cg0  = g * 64;
    const float* emb = (var ? pemb : nemb) + b * 64 * 1024;
    const int tid = threadIdx.x;

    for (int i = tid; i < 4096; i += 256) {
        int c = i >> 6, e = i & 63;
        Ws[c * 65 + e] = W[(cg0 + c) * 64 + e];
    }
    for (int i = tid; i < 4096; i += 256) {
        int e = i >> 6, t = i & 63;
        Es[e * 68 + t] = emb[e * 1024 + t0 + t];
    }
    __syncthreads();

    const int c = tid & 63, tg = tid >> 6;   // tg 0..3, 16 t each
    ull acc2[8];
    #pragma unroll
    for (int i = 0; i < 8; i++) acc2[i] = 0ULL;

    #pragma unroll 4
    for (int e = 0; e < 64; e++) {
        float w = Ws[c * 65 + e];
        ull w2 = pk2(w, w);
        const ull* row = (const ull*)(Es + e * 68 + tg * 16);
        #pragma unroll
        for (int k = 0; k < 8; k++) acc2[k] = fma2(w2, row[k], acc2[k]);
    }
    __syncthreads();
    const float* qk = qkv + (size_t)b * 1536 * 1024 + (size_t)cg0 * 1024 + t0;
    for (int i = tid; i < 4096; i += 256) {
        int cc = i >> 6, t = i & 63;
        Es[cc * 68 + t] = qk[cc * 1024 + t];
    }
    __syncthreads();

    __half* dst;
    if (var == 0) dst = (part == 0 ? g_Qn : (part == 1 ? g_Kn : g_Vn));
    else          dst = (part == 0 ? g_Qf : (part == 1 ? g_Kf : g_Vf));
    dst += (size_t)(b * NHEAD + head) * T_LEN * CH;
    const float sc = (part == 0) ? QSCALE : 1.0f;   // scale^2 * log2e folded into Q
    #pragma unroll
    for (int k = 0; k < 8; k++) {
        float a0, a1;
        upk2(acc2[k], a0, a1);
        int t = tg * 16 + 2 * k;
        dst[(t0 + t)     * CH + c] = __float2half_rn((a0 + Es[c * 68 + t])     * sc);
        dst[(t0 + t + 1) * CH + c] = __float2half_rn((a1 + Es[c * 68 + t + 1]) * sc);
    }
}

// ---------------- merged flash kernel: fp16 m16n8k16 mma ----------------
// z=0: null attention over UNCOVERED tokens only (gather via g_uncidx, full K);
// z=1..8: fg object z-1 (region-restricted rows AND cols).
// 128 threads = 4 warps; warp w owns q-rows [16w, 16w+16).
// All smem row pitches 144B (36 words): 16B-aligned cp.async dsts;
// K/Q/P fragment banks {4lg+la} conflict-free; ldmatrix.trans phases
// hit banks (4i+4nt) mod 32 -> conflict-free.
__global__ __launch_bounds__(128, 4)
void flash_kernel() {
    extern __shared__ float sm[];
    const int z  = blockIdx.z;
    const int bh = blockIdx.y;
    const int qbase = blockIdx.x * QT;
    int i0 = 0, j00 = 0, rw = 32;
    int nR = T_LEN;          // k-side extent
    int nQ;                  // q-side extent
    const int* idxp = 0;
    const __half *Qp, *Kp, *Vp;
    if (z == 0) {
        const int b = bh >> 3;
        nQ = g_unccnt[b];
        if (qbase >= nQ) return;
        idxp = g_uncidx + b * T_LEN;
        Qp = g_Qn + (size_t)bh * T_LEN * CH;
        Kp = g_Kn + (size_t)bh * T_LEN * CH;
        Vp = g_Vn + (size_t)bh * T_LEN * CH;
    } else {
        const int o = z - 1, b = bh >> 3;
        const int* box = g_regbox + (b * NOBJ + o) * 4;
        i0 = box[0]; j00 = box[2];
        rw = box[3] - j00;
        nR = (box[1] - i0) * rw;
        nQ = nR;
        if (qbase >= nQ) return;
        Qp = g_Qf + (size_t)bh * T_LEN * CH;
        Kp = g_Kf + (size_t)bh * T_LEN * CH;
        Vp = g_Vf + (size_t)bh * T_LEN * CH;
    }
    const int tid  = threadIdx.x;
    const int w    = tid >> 5, lane = tid & 31;
    const int la   = lane & 3, lg = lane >> 2;

    unsigned* QPu = (unsigned*)sm;                       // pitch 36 words
    const unsigned* Ku = (const unsigned*)((char*)sm + KS_B);
    const unsigned smem_u = (unsigned)__cvta_generic_to_shared(sm);

    // ---- issue Q + K0/V0 cp.asyncs together (rows are 128B = 8 chunks of 16B) ----
    #pragma unroll
    for (int it = 0; it < 4; it++) {
        int idx = tid + it * 128;
        int r = idx >> 3, c4 = idx & 7;
        int u = qbase + r;
        const __half* src = Qp;
        int bytes = 0;
        if (u < nQ) {
            int t = (z == 0) ? idxp[u] : ((i0 + u / rw) * 32 + j00 + u % rw);
            src = Qp + (size_t)t * CH + c4 * 8;
            bytes = 16;
        }
        cp16(smem_u + QP_B + r * 144 + c4 * 16, src, bytes);
    }
    #pragma unroll
    for (int it = 0; it < 4; it++) {
        int idx = tid + it * 128;
        int s = idx >> 3, c4 = idx & 7;
        const __half *ksrc = Kp, *vsrc = Vp;
        int bytes = 0;
        if (s < nR) {
            int t = (z == 0) ? s : ((i0 + s / rw) * 32 + j00 + s % rw);
            ksrc = Kp + (size_t)t * CH + c4 * 8;
            vsrc = Vp + (size_t)t * CH + c4 * 8;
            bytes = 16;
        }
        cp16(smem_u + KS_B + s * 144 + c4 * 16, ksrc, bytes);
        cp16(smem_u + VS_B + s * 144 + c4 * 16, vsrc, bytes);
    }
    CP_COMMIT();
    CP_WAIT0();
    __syncthreads();

    // ---- hoist Q A-fragments to registers; QP region becomes the P buffer ----
    unsigned qa[4][4];
    {
        const int arow = (16 * w + lg) * 36;
        #pragma unroll
        for (int ks = 0; ks < 4; ks++) {
            qa[ks][0] = QPu[arow + 8 * ks + la];
            qa[ks][1] = QPu[arow + 8 * 36 + 8 * ks + la];
            qa[ks][2] = QPu[arow + 8 * ks + la + 4];
            qa[ks][3] = QPu[arow + 8 * 36 + 8 * ks + la + 4];
        }
    }
    // (each warp only touches its own 16 QP rows from here on)

    float o[8][4];
    #pragma unroll
    for (int nt = 0; nt < 8; nt++) { o[nt][0] = o[nt][1] = o[nt][2] = o[nt][3] = 0.0f; }
    float m_lo = -1e30f, m_hi = -1e30f, l_lo = 0.0f, l_hi = 0.0f;

    const int plo = (16 * w + lg) * 36;        // this thread's P rows (word index)
    const int phi = plo + 8 * 36;
    const int vlane = lane & 15;               // ldmatrix x2 row-provider

    const int nkt = (nR + KT - 1) / KT;
    for (int kt = 0; kt < nkt; kt++) {
        if (kt > 0) {
            __syncthreads();                    // prior tile fully consumed
            #pragma unroll
            for (int it = 0; it < 4; it++) {
                int idx = tid + it * 128;
                int s = idx >> 3, c4 = idx & 7;
                int sg = kt * KT + s;
                const __half *ksrc = Kp, *vsrc = Vp;
                int bytes = 0;
                if (sg < nR) {
                    int t = (z == 0) ? sg : ((i0 + sg / rw) * 32 + j00 + sg % rw);
                    ksrc = Kp + (size_t)t * CH + c4 * 8;
                    vsrc = Vp + (size_t)t * CH + c4 * 8;
                    bytes = 16;
                }
                cp16(smem_u + KS_B + s * 144 + c4 * 16, ksrc, bytes);
                cp16(smem_u + VS_B + s * 144 + c4 * 16, vsrc, bytes);
            }
            CP_COMMIT();
            CP_WAIT0();
            __syncthreads();
        }

        // ---- S = Q K^T via fp16 mma (acc[nt] covers cols [8nt, 8nt+8)) ----
        float acc[8][4];
        #pragma unroll
        for (int nt = 0; nt < 8; nt++) { acc[nt][0] = acc[nt][1] = acc[nt][2] = acc[nt][3] = 0.0f; }
        #pragma unroll
        for (int ks = 0; ks < 4; ks++) {
            #pragma unroll
            for (int nt = 0; nt < 8; nt++) {
                unsigned b0 = Ku[(8 * nt + lg) * 36 + 8 * ks + la];
                unsigned b1 = Ku[(8 * nt + lg) * 36 + 8 * ks + la + 4];
                MMA_F16(acc[nt], qa[ks][0], qa[ks][1], qa[ks][2], qa[ks][3], b0, b1);
            }
        }

        // ---- mask columns beyond region (fg only) ----
        if (z != 0) {
            #pragma unroll
            for (int nt = 0; nt < 8; nt++) {
                int sc = kt * KT + 8 * nt + 2 * la;
                if (sc >= nR)     { acc[nt][0] = -1e30f; acc[nt][2] = -1e30f; }
                if (sc + 1 >= nR) { acc[nt][1] = -1e30f; acc[nt][3] = -1e30f; }
            }
        }

        // ---- online softmax, base-2 (rows lg / lg+8; reduce across quad lanes) ----
        float mx0 = -1e30f, mx1 = -1e30f;
        #pragma unroll
        for (int nt = 0; nt < 8; nt++) {
            mx0 = fmaxf(mx0, fmaxf(acc[nt][0], acc[nt][1]));
            mx1 = fmaxf(mx1, fmaxf(acc[nt][2], acc[nt][3]));
        }
        mx0 = fmaxf(mx0, __shfl_xor_sync(0xffffffffu, mx0, 1));
        mx0 = fmaxf(mx0, __shfl_xor_sync(0xffffffffu, mx0, 2));
        mx1 = fmaxf(mx1, __shfl_xor_sync(0xffffffffu, mx1, 1));
        mx1 = fmaxf(mx1, __shfl_xor_sync(0xffffffffu, mx1, 2));
        float mn0 = fmaxf(m_lo, mx0), mn1 = fmaxf(m_hi, mx1);
        float co0 = exp2f(m_lo - mn0), co1 = exp2f(m_hi - mn1);
        m_lo = mn0; m_hi = mn1;
        float rs0 = 0.0f, rs1 = 0.0f;
        #pragma unroll
        for (int nt = 0; nt < 8; nt++) {
            acc[nt][0] = exp2f(acc[nt][0] - mn0); rs0 += acc[nt][0];
            acc[nt][1] = exp2f(acc[nt][1] - mn0); rs0 += acc[nt][1];
            acc[nt][2] = exp2f(acc[nt][2] - mn1); rs1 += acc[nt][2];
            acc[nt][3] = exp2f(acc[nt][3] - mn1); rs1 += acc[nt][3];
        }
        rs0 += __shfl_xor_sync(0xffffffffu, rs0, 1);
        rs0 += __shfl_xor_sync(0xffffffffu, rs0, 2);
        rs1 += __shfl_xor_sync(0xffffffffu, rs1, 1);
        rs1 += __shfl_xor_sync(0xffffffffu, rs1, 2);
        l_lo = l_lo * co0 + rs0;
        l_hi = l_hi * co1 + rs1;
        #pragma unroll
        for (int nt = 0; nt < 8; nt++) {
            o[nt][0] *= co0; o[nt][1] *= co0;
            o[nt][2] *= co1; o[nt][3] *= co1;
        }

        // ---- stage P (fp16) through warp-private smem rows ----
        #pragma unroll
        for (int nt = 0; nt < 8; nt++) {
            __half2 h0 = __floats2half2_rn(acc[nt][0], acc[nt][1]);
            __half2 h1 = __floats2half2_rn(acc[nt][2], acc[nt][3]);
            QPu[plo + 4 * nt + la] = *(unsigned*)&h0;
            QPu[phi + 4 * nt + la] = *(unsigned*)&h1;
        }
        __syncwarp();

        // ---- O += P V : A from own P rows; B via ldmatrix.x2.trans from row-major V ----
        #pragma unroll
        for (int ks = 0; ks < 4; ks++) {
            unsigned a0 = QPu[plo + 8 * ks + la];
            unsigned a1 = QPu[phi + 8 * ks + la];
            unsigned a2 = QPu[plo + 8 * ks + la + 4];
            unsigned a3 = QPu[phi + 8 * ks + la + 4];
            unsigned vbase = smem_u + VS_B + (16 * ks + vlane) * 144;
            #pragma unroll
            for (int nt = 0; nt < 8; nt++) {
                unsigned b0, b1;
                LDSM_X2_T(b0, b1, vbase + nt * 16);
                MMA_F16(o[nt], a0, a1, a2, a3, b0, b1);
            }
        }
        __syncwarp();      // P reads done before next tile's softmax overwrites
    }

    // ---- epilogue ----
    float inv0 = 1.0f / l_lo, inv1 = 1.0f / l_hi;
    int u_lo = qbase + 16 * w + lg;
    int u_hi = u_lo + 8;
    if (z == 0) {
        float* Op = g_anull + (size_t)bh * T_LEN * CH;
        int t_lo = 0, t_hi = 0;
        if (u_lo < nQ) t_lo = idxp[u_lo];
        if (u_hi < nQ) t_hi = idxp[u_hi];
        #pragma unroll
        for (int nt = 0; nt < 8; nt++) {
            int ch = 8 * nt + 2 * la;
            if (u_lo < nQ)
                *(float2*)(Op + (size_t)t_lo * CH + ch) = make_float2(o[nt][0] * inv0, o[nt][1] * inv0);
            if (u_hi < nQ)
                *(float2*)(Op + (size_t)t_hi * CH + ch) = make_float2(o[nt][2] * inv1, o[nt][3] * inv1);
        }
    } else {
        float* Ap = g_afg + (size_t)bh * T_LEN * CH;
        int t_lo = 0, t_hi = 0;
        if (u_lo < nQ) t_lo = (i0 + u_lo / rw) * 32 + j00 + u_lo % rw;
        if (u_hi < nQ) t_hi = (i0 + u_hi / rw) * 32 + j00 + u_hi % rw;
        #pragma unroll
        for (int nt = 0; nt < 8; nt++) {
            int ch = 8 * nt + 2 * la;
            if (u_lo < nQ) {
                atomicAdd(Ap + (size_t)t_lo * CH + ch,     o[nt][0] * inv0);
                atomicAdd(Ap + (size_t)t_lo * CH + ch + 1, o[nt][1] * inv0);
            }
            if (u_hi < nQ) {
                atomicAdd(Ap + (size_t)t_hi * CH + ch,     o[nt][2] * inv1);
                atomicAdd(Ap + (size_t)t_hi * CH + ch + 1, o[nt][3] * inv1);
            }
        }
    }
}

// ---------------- finalize: select + divide + transpose to (bs, 512, T) ----------------
__global__ __launch_bounds__(256)
void finalize_kernel(float* __restrict__ out) {
    __shared__ float smf[64 * 65];
    const int bh = blockIdx.y;
    const int t0 = blockIdx.x * 64;
    const int b = bh >> 3, h = bh & 7;
    const float* An = g_anull + (size_t)bh * T_LEN * CH;
    const float* Af = g_afg   + (size_t)bh * T_LEN * CH;
    const float* Cn = g_cnt + b * T_LEN;
    const int tid = threadIdx.x;
    for (int i = tid; i < 4096; i += 256) {
        int tt = i >> 6, c = i & 63;
        int t = t0 + tt;
        float cnt = Cn[t];
        float v = (cnt > 0.5f) ? Af[(size_t)t * CH + c] / cnt : An[(size_t)t * CH + c];
        smf[tt * 65 + c] = v;
    }
    __syncthreads();
    float* op = out + (size_t)b * 512 * 1024 + (size_t)h * 64 * 1024 + t0;
    for (int i = tid; i < 4096; i += 256) {
        int c = i >> 6, tt = i & 63;
        op[(size_t)c * 1024 + tt] = smf[tt * 65 + c];
    }
}

// ---------------- launch ----------------
extern "C" void kernel_launch(void* const* d_in, const int* in_sizes, int n_in,
                              void* d_out, int out_size) {
    const float* qkv  = (const float*)d_in[0];
    const float* bb   = (const float*)d_in[1];
    const float* nemb = (const float*)d_in[2];
    const float* pemb = (const float*)d_in[3];
    const float* W    = (const float*)d_in[4];
    float* out = (float*)d_out;

    cudaFuncSetAttribute(flash_kernel, cudaFuncAttributeMaxDynamicSharedMemorySize, SMEM_BYTES);

    init_kernel<<<256, 256>>>(bb);
    combine_kernel<<<dim3(24, 16, 8), 256>>>(qkv, nemb, pemb, W);
    flash_kernel<<<dim3(T_LEN / QT, HH_TOT, 1 + NOBJ), 128, SMEM_BYTES>>>();
    finalize_kernel<<<dim3(T_LEN / 64, HH_TOT), 256>>>(out);
}